// round 2
// baseline (speedup 1.0000x reference)
#include <cuda_runtime.h>
#include <cstddef>

#define B_  32
#define N_  4096
#define DIN 256
#define D_  256
#define S_  16
#define H_  512
#define EPS 1e-5f

// ---------------- scratch (no runtime allocation allowed) ----------------
__device__ float g_xln [(size_t)B_ * N_ * DIN];   // 128 MB
__device__ float g_k   [(size_t)B_ * N_ * D_];    // 128 MB
__device__ float g_v   [(size_t)B_ * N_ * D_];    // 128 MB
__device__ float g_slots[B_ * S_ * D_];
__device__ float g_sn   [B_ * S_ * D_];
__device__ float g_q    [B_ * S_ * D_];
__device__ float g_attn [B_ * S_ * N_];           // 8 MB
__device__ float g_upd  [B_ * S_ * D_];
__device__ float g_gi   [B_ * S_ * 3 * D_];
__device__ float g_gh   [B_ * S_ * 3 * D_];
__device__ float g_h    [B_ * S_ * D_];
__device__ float g_m    [B_ * S_ * D_];
__device__ float g_t    [B_ * S_ * H_];

// ---------------- slots init: slots = mu + sigma * noise ----------------
__global__ void slots_init_kernel(const float* __restrict__ noise,
                                  const float* __restrict__ mu,
                                  const float* __restrict__ sigma,
                                  float* __restrict__ slots) {
    int i = blockIdx.x * 256 + threadIdx.x;      // grid covers B*S*D exactly
    int d = i & (D_ - 1);
    slots[i] = mu[d] + sigma[d] * noise[i];
}

// ---------------- LayerNorm over rows of length 256 (warp per row) ------
__global__ void ln_rows_kernel(const float* __restrict__ X,
                               const float* __restrict__ gg,
                               const float* __restrict__ bb,
                               float* __restrict__ Y, int rows) {
    int warp = threadIdx.x >> 5, lane = threadIdx.x & 31;
    int row = blockIdx.x * 8 + warp;
    if (row >= rows) return;
    const float4* x4 = (const float4*)(X + (size_t)row * 256);
    float4 a = x4[lane];
    float4 c = x4[lane + 32];
    float s  = a.x + a.y + a.z + a.w + c.x + c.y + c.z + c.w;
    float s2 = a.x*a.x + a.y*a.y + a.z*a.z + a.w*a.w
             + c.x*c.x + c.y*c.y + c.z*c.z + c.w*c.w;
    #pragma unroll
    for (int o = 16; o; o >>= 1) {
        s  += __shfl_xor_sync(0xffffffffu, s,  o);
        s2 += __shfl_xor_sync(0xffffffffu, s2, o);
    }
    float mean = s * (1.0f / 256.0f);
    float var  = s2 * (1.0f / 256.0f) - mean * mean;
    float rstd = rsqrtf(var + EPS);
    const float4* g4 = (const float4*)gg;
    const float4* b4 = (const float4*)bb;
    float4 ga = g4[lane], gc = g4[lane + 32];
    float4 ba = b4[lane], bc = b4[lane + 32];
    float4 o1, o2;
    o1.x = (a.x - mean) * rstd * ga.x + ba.x;
    o1.y = (a.y - mean) * rstd * ga.y + ba.y;
    o1.z = (a.z - mean) * rstd * ga.z + ba.z;
    o1.w = (a.w - mean) * rstd * ga.w + ba.w;
    o2.x = (c.x - mean) * rstd * gc.x + bc.x;
    o2.y = (c.y - mean) * rstd * gc.y + bc.y;
    o2.z = (c.z - mean) * rstd * gc.z + bc.z;
    o2.w = (c.w - mean) * rstd * gc.w + bc.w;
    float4* y4 = (float4*)(Y + (size_t)row * 256);
    y4[lane] = o1;
    y4[lane + 32] = o2;
}

// ---------------- generic fp32 GEMM: C = A[M,K] * W[N,K]^T + bias --------
// 128x128 block tile, BK=8, 256 threads, 8x8 microtile.
template <bool RELU, bool ADD>
__global__ void gemm_nt_kernel(const float* __restrict__ A,
                               const float* __restrict__ W,
                               const float* __restrict__ bias,
                               const float* __restrict__ Addm,
                               float* __restrict__ C,
                               int M, int Nn, int K) {
    __shared__ float As[8][128];
    __shared__ float Bs[8][128];
    int tid = threadIdx.x;
    int tx = tid & 15, ty = tid >> 4;
    int m0 = blockIdx.y * 128, n0 = blockIdx.x * 128;

    float acc[8][8];
    #pragma unroll
    for (int i = 0; i < 8; i++)
        #pragma unroll
        for (int j = 0; j < 8; j++) acc[i][j] = 0.0f;

    int lrow = tid >> 1;            // 0..127
    int lk4  = (tid & 1) * 4;       // 0 or 4

    for (int k0 = 0; k0 < K; k0 += 8) {
        float4 av = make_float4(0.f, 0.f, 0.f, 0.f);
        int gm = m0 + lrow;
        if (gm < M) av = *(const float4*)&A[(size_t)gm * K + k0 + lk4];
        As[lk4 + 0][lrow] = av.x; As[lk4 + 1][lrow] = av.y;
        As[lk4 + 2][lrow] = av.z; As[lk4 + 3][lrow] = av.w;

        float4 bv = make_float4(0.f, 0.f, 0.f, 0.f);
        int gn = n0 + lrow;
        if (gn < Nn) bv = *(const float4*)&W[(size_t)gn * K + k0 + lk4];
        Bs[lk4 + 0][lrow] = bv.x; Bs[lk4 + 1][lrow] = bv.y;
        Bs[lk4 + 2][lrow] = bv.z; Bs[lk4 + 3][lrow] = bv.w;
        __syncthreads();

        #pragma unroll
        for (int kk = 0; kk < 8; kk++) {
            float4 a0 = *(float4*)&As[kk][ty * 8];
            float4 a1 = *(float4*)&As[kk][ty * 8 + 4];
            float4 b0 = *(float4*)&Bs[kk][tx * 8];
            float4 b1 = *(float4*)&Bs[kk][tx * 8 + 4];
            float ar[8] = {a0.x, a0.y, a0.z, a0.w, a1.x, a1.y, a1.z, a1.w};
            float br[8] = {b0.x, b0.y, b0.z, b0.w, b1.x, b1.y, b1.z, b1.w};
            #pragma unroll
            for (int i = 0; i < 8; i++)
                #pragma unroll
                for (int j = 0; j < 8; j++)
                    acc[i][j] += ar[i] * br[j];
        }
        __syncthreads();
    }

    #pragma unroll
    for (int i = 0; i < 8; i++) {
        int gm = m0 + ty * 8 + i;
        if (gm >= M) continue;
        #pragma unroll
        for (int j = 0; j < 8; j++) {
            int gn = n0 + tx * 8 + j;
            if (gn >= Nn) continue;
            float v = acc[i][j] + bias[gn];
            if (RELU) v = fmaxf(v, 0.0f);
            if (ADD)  v += Addm[(size_t)gm * Nn + gn];
            C[(size_t)gm * Nn + gn] = v;
        }
    }
}

// ---------------- fused logits + softmax over S ---------------------------
// logits[b,s,n] = (k[b,n,:] . q[b,s,:]) / 16 ; attn = softmax over s.
// grid (N/128, B), block 256: 128 n's, d-dim split in two halves per thread.
#define ATTN_KSM_STRIDE 257
#define ATTN_SMEM_BYTES ((128 * ATTN_KSM_STRIDE + S_ * 256) * 4)

__global__ void attn_kernel(const float* __restrict__ Kmat,
                            const float* __restrict__ Q,
                            float* __restrict__ attn) {
    extern __shared__ float sm[];
    float* ksm = sm;                          // [128][257]  (n-major, pad)
    float* qsm = sm + 128 * ATTN_KSM_STRIDE;  // [16][256]
    int b = blockIdx.y, n0 = blockIdx.x * 128;
    const float* kb = Kmat + ((size_t)b * N_ + n0) * D_;
    const float* qb = Q + (size_t)b * S_ * D_;
    int tid = threadIdx.x;

    for (int i = tid; i < S_ * 256; i += 256) qsm[i] = qb[i];
    for (int e4 = tid; e4 < 128 * 64; e4 += 256) {
        int nl = e4 >> 6;
        int d4 = (e4 & 63) * 4;
        float4 v = *(const float4*)&kb[(size_t)nl * D_ + d4];
        ksm[nl * ATTN_KSM_STRIDE + d4 + 0] = v.x;
        ksm[nl * ATTN_KSM_STRIDE + d4 + 1] = v.y;
        ksm[nl * ATTN_KSM_STRIDE + d4 + 2] = v.z;
        ksm[nl * ATTN_KSM_STRIDE + d4 + 3] = v.w;
    }
    __syncthreads();

    int n = tid & 127, half = tid >> 7;
    int dbase = half * 128;
    float acc[S_];
    #pragma unroll
    for (int s = 0; s < S_; s++) acc[s] = 0.0f;

    const float* krow = ksm + n * ATTN_KSM_STRIDE + dbase;
    #pragma unroll 4
    for (int d = 0; d < 128; d++) {
        float kv = krow[d];
        #pragma unroll
        for (int s = 0; s < S_; s++)
            acc[s] += kv * qsm[s * 256 + dbase + d];
    }

    __syncthreads();                 // done with ksm contents; reuse as reduce buf
    float* red = ksm;
    if (half == 1) {
        #pragma unroll
        for (int s = 0; s < S_; s++) red[s * 128 + n] = acc[s];
    }
    __syncthreads();
    if (half == 0) {
        const float scale = 0.0625f;   // D^-0.5 = 1/16
        float mx = -1e30f;
        #pragma unroll
        for (int s = 0; s < S_; s++) {
            acc[s] = (acc[s] + red[s * 128 + n]) * scale;
            mx = fmaxf(mx, acc[s]);
        }
        float sum = 0.0f;
        #pragma unroll
        for (int s = 0; s < S_; s++) { acc[s] = __expf(acc[s] - mx); sum += acc[s]; }
        float inv = 1.0f / sum;
        #pragma unroll
        for (int s = 0; s < S_; s++)
            attn[((size_t)b * S_ + s) * N_ + n0 + n] = acc[s] * inv;
    }
}

// ---------------- updates = einsum('bsn,bnd->bsd', attn, v) ---------------
// grid (D/64, B), block 256: thread = (s, 16 d-groups of 4), reduce over n.
__global__ void updates_kernel(const float* __restrict__ attn,
                               const float* __restrict__ V,
                               float* __restrict__ upd) {
    __shared__ float vt[64][64];
    __shared__ float at[S_][64];
    int b = blockIdx.y, d0 = blockIdx.x * 64;
    const float* vb = V + (size_t)b * N_ * D_;
    const float* ab = attn + (size_t)b * S_ * N_;
    int tid = threadIdx.x;
    int s = tid >> 4, dg = tid & 15;
    float acc0 = 0.f, acc1 = 0.f, acc2 = 0.f, acc3 = 0.f;

    for (int nn0 = 0; nn0 < N_; nn0 += 64) {
        __syncthreads();
        for (int e4 = tid; e4 < 1024; e4 += 256) {
            int nl = e4 >> 4;
            int dq = (e4 & 15) * 4;
            float4 v = *(const float4*)&vb[(size_t)(nn0 + nl) * D_ + d0 + dq];
            *(float4*)&vt[nl][dq] = v;
        }
        for (int e = tid; e < S_ * 64; e += 256) {
            int sl = e >> 6, nl = e & 63;
            at[sl][nl] = ab[(size_t)sl * N_ + nn0 + nl];
        }
        __syncthreads();
        #pragma unroll 4
        for (int nn = 0; nn < 64; nn++) {
            float a = at[s][nn];
            float4 v = *(float4*)&vt[nn][dg * 4];
            acc0 += a * v.x; acc1 += a * v.y; acc2 += a * v.z; acc3 += a * v.w;
        }
    }
    float* o = upd + ((size_t)b * S_ + s) * D_ + d0 + dg * 4;
    o[0] = acc0; o[1] = acc1; o[2] = acc2; o[3] = acc3;
}

// ---------------- GRU pointwise -------------------------------------------
__device__ __forceinline__ float sigmoidf(float x) { return 1.0f / (1.0f + __expf(-x)); }

__global__ void gru_pw_kernel(const float* __restrict__ gi,
                              const float* __restrict__ gh,
                              const float* __restrict__ hprev,
                              float* __restrict__ h) {
    int i = blockIdx.x * 256 + threadIdx.x;     // covers B*S*D exactly
    int row = i >> 8, col = i & 255;
    const float* gir = gi + (size_t)row * 768;
    const float* ghr = gh + (size_t)row * 768;
    float r = sigmoidf(gir[col]       + ghr[col]);
    float z = sigmoidf(gir[col + 256] + ghr[col + 256]);
    float n = tanhf(gir[col + 512] + r * ghr[col + 512]);
    h[i] = (1.0f - z) * n + z * hprev[i];
}

__global__ void copy_kernel(const float* __restrict__ s, float* __restrict__ d, int n) {
    int i = blockIdx.x * 256 + threadIdx.x;
    if (i < n) d[i] = s[i];
}

// ---------------- host side ------------------------------------------------
static void launch_gemm(const float* A, const float* W, const float* bias,
                        const float* Add, float* C, int M, int Nn, int K, int mode) {
    dim3 grid((Nn + 127) / 128, (M + 127) / 128);
    if (mode == 1)
        gemm_nt_kernel<true, false><<<grid, 256>>>(A, W, bias, nullptr, C, M, Nn, K);
    else if (mode == 2)
        gemm_nt_kernel<false, true><<<grid, 256>>>(A, W, bias, Add, C, M, Nn, K);
    else
        gemm_nt_kernel<false, false><<<grid, 256>>>(A, W, bias, nullptr, C, M, Nn, K);
}

extern "C" void kernel_launch(void* const* d_in, const int* in_sizes, int n_in,
                              void* d_out, int out_size) {
    const float* inputs     = (const float*)d_in[0];
    const float* init_noise = (const float*)d_in[1];
    const float* slots_mu   = (const float*)d_in[2];
    const float* slots_sig  = (const float*)d_in[3];
    const float* ln_in_g    = (const float*)d_in[4];
    const float* ln_in_b    = (const float*)d_in[5];
    const float* ln_s_g     = (const float*)d_in[6];
    const float* ln_s_b     = (const float*)d_in[7];
    const float* ln_m_g     = (const float*)d_in[8];
    const float* ln_m_b     = (const float*)d_in[9];
    const float* Wk         = (const float*)d_in[10];
    const float* bk         = (const float*)d_in[11];
    const float* Wv         = (const float*)d_in[12];
    const float* bv         = (const float*)d_in[13];
    const float* Wq         = (const float*)d_in[14];
    const float* bq         = (const float*)d_in[15];
    const float* W_ih       = (const float*)d_in[16];
    const float* W_hh       = (const float*)d_in[17];
    const float* b_ih       = (const float*)d_in[18];
    const float* b_hh       = (const float*)d_in[19];
    const float* W1         = (const float*)d_in[20];
    const float* b1         = (const float*)d_in[21];
    const float* W2         = (const float*)d_in[22];
    const float* b2         = (const float*)d_in[23];
    float* out = (float*)d_out;

    float *xln, *k, *v, *slots, *sn, *q, *attn, *upd, *gi, *gh, *h, *m, *t;
    cudaGetSymbolAddress((void**)&xln,   g_xln);
    cudaGetSymbolAddress((void**)&k,     g_k);
    cudaGetSymbolAddress((void**)&v,     g_v);
    cudaGetSymbolAddress((void**)&slots, g_slots);
    cudaGetSymbolAddress((void**)&sn,    g_sn);
    cudaGetSymbolAddress((void**)&q,     g_q);
    cudaGetSymbolAddress((void**)&attn,  g_attn);
    cudaGetSymbolAddress((void**)&upd,   g_upd);
    cudaGetSymbolAddress((void**)&gi,    g_gi);
    cudaGetSymbolAddress((void**)&gh,    g_gh);
    cudaGetSymbolAddress((void**)&h,     g_h);
    cudaGetSymbolAddress((void**)&m,     g_m);
    cudaGetSymbolAddress((void**)&t,     g_t);

    cudaFuncSetAttribute(attn_kernel, cudaFuncAttributeMaxDynamicSharedMemorySize,
                         ATTN_SMEM_BYTES);

    const int BND = B_ * N_;          // 131072 rows
    const int BSD = B_ * S_ * D_;     // 131072 elements
    const int BSN = B_ * S_ * N_;     // 2097152 elements

    // slots = mu + sigma * noise
    slots_init_kernel<<<BSD / 256, 256>>>(init_noise, slots_mu, slots_sig, slots);
    // x = LN(inputs); k = x Wk^T + bk; v = x Wv^T + bv
    ln_rows_kernel<<<BND / 8, 256>>>(inputs, ln_in_g, ln_in_b, xln, BND);
    launch_gemm(xln, Wk, bk, nullptr, k, BND, D_, DIN, 0);
    launch_gemm(xln, Wv, bv, nullptr, v, BND, D_, DIN, 0);

    for (int it = 0; it < 3; it++) {
        ln_rows_kernel<<<(B_ * S_ + 7) / 8, 256>>>(slots, ln_s_g, ln_s_b, sn, B_ * S_);
        launch_gemm(sn, Wq, bq, nullptr, q, B_ * S_, D_, D_, 0);
        attn_kernel<<<dim3(N_ / 128, B_), 256, ATTN_SMEM_BYTES>>>(k, q, attn);
        updates_kernel<<<dim3(D_ / 64, B_), 256>>>(attn, v, upd);
        launch_gemm(upd,   W_ih, b_ih, nullptr, gi, B_ * S_, 3 * D_, D_, 0);
        launch_gemm(slots, W_hh, b_hh, nullptr, gh, B_ * S_, 3 * D_, D_, 0);
        gru_pw_kernel<<<BSD / 256, 256>>>(gi, gh, slots, h);
        ln_rows_kernel<<<(B_ * S_ + 7) / 8, 256>>>(h, ln_m_g, ln_m_b, m, B_ * S_);
        launch_gemm(m, W1, b1, nullptr, t, B_ * S_, H_, D_, 1);        // ReLU
        launch_gemm(t, W2, b2, h, slots, B_ * S_, D_, H_, 2);          // + h residual
    }

    // output: (slots, attn) flattened
    copy_kernel<<<BSD / 256, 256>>>(slots, out, BSD);
    if (out_size >= BSD + BSN)
        copy_kernel<<<(BSN + 255) / 256, 256>>>(attn, out + (out_size - BSN), BSN);
}

// round 3
// speedup vs baseline: 3.6933x; 3.6933x over previous
#include <cuda_runtime.h>
#include <cstddef>

#define B_  32
#define N_  4096
#define DIN 256
#define D_  256
#define S_  16
#define H_  512
#define EPS 1e-5f
#define SCALE 0.0625f
#define NTILES 32            // N_/128
#define XSTR 260

// ---------------- scratch (no runtime allocation allowed) ----------------
__device__ float g_xln [(size_t)B_ * N_ * DIN];          // 128 MB
__device__ float g_slots[B_ * S_ * D_];
__device__ float g_sn   [B_ * S_ * D_];
__device__ float g_qk   [B_ * S_ * DIN];
__device__ float g_ct   [B_ * S_];
__device__ float g_uv   [B_ * S_ * DIN];
__device__ float g_r    [B_ * S_];
__device__ float g_part [(size_t)B_ * NTILES * S_ * DIN]; // 16.8 MB
__device__ float g_rpart[B_ * NTILES * S_];
__device__ float g_gi   [B_ * S_ * 3 * D_];
__device__ float g_gh   [B_ * S_ * 3 * D_];
__device__ float g_h    [B_ * S_ * D_];
__device__ float g_m    [B_ * S_ * D_];
__device__ float g_t    [B_ * S_ * H_];
__device__ float g_Wqk  [DIN * D_];      // [j,d] = scale * sum_e Wk[e,j] Wq[e,d]
__device__ float g_Wiv  [3 * D_ * DIN];  // [r,j] = sum_e W_ih[r,e] Wv[e,j]
__device__ float g_us   [D_];
__device__ float g_bqk  [DIN];
__device__ float g_biv  [3 * D_];
__device__ float g_c0   [1];

// ---------------- slots init: slots = mu + sigma * noise ----------------
__global__ void slots_init_kernel(const float* __restrict__ noise,
                                  const float* __restrict__ mu,
                                  const float* __restrict__ sigma,
                                  float* __restrict__ slots) {
    int i = blockIdx.x * 256 + threadIdx.x;
    int d = i & (D_ - 1);
    slots[i] = mu[d] + sigma[d] * noise[i];
}

// ---------------- LayerNorm over rows of length 256 (warp per row) ------
__global__ void ln_rows_kernel(const float* __restrict__ X,
                               const float* __restrict__ gg,
                               const float* __restrict__ bb,
                               float* __restrict__ Y, int rows) {
    int warp = threadIdx.x >> 5, lane = threadIdx.x & 31;
    int row = blockIdx.x * 8 + warp;
    if (row >= rows) return;
    const float4* x4 = (const float4*)(X + (size_t)row * 256);
    float4 a = x4[lane];
    float4 c = x4[lane + 32];
    float s  = a.x + a.y + a.z + a.w + c.x + c.y + c.z + c.w;
    float s2 = a.x*a.x + a.y*a.y + a.z*a.z + a.w*a.w
             + c.x*c.x + c.y*c.y + c.z*c.z + c.w*c.w;
    #pragma unroll
    for (int o = 16; o; o >>= 1) {
        s  += __shfl_xor_sync(0xffffffffu, s,  o);
        s2 += __shfl_xor_sync(0xffffffffu, s2, o);
    }
    float mean = s * (1.0f / 256.0f);
    float var  = s2 * (1.0f / 256.0f) - mean * mean;
    float rstd = rsqrtf(var + EPS);
    const float4* g4 = (const float4*)gg;
    const float4* b4 = (const float4*)bb;
    float4 ga = g4[lane], gc = g4[lane + 32];
    float4 ba = b4[lane], bc = b4[lane + 32];
    float4 o1, o2;
    o1.x = (a.x - mean) * rstd * ga.x + ba.x;
    o1.y = (a.y - mean) * rstd * ga.y + ba.y;
    o1.z = (a.z - mean) * rstd * ga.z + ba.z;
    o1.w = (a.w - mean) * rstd * ga.w + ba.w;
    o2.x = (c.x - mean) * rstd * gc.x + bc.x;
    o2.y = (c.y - mean) * rstd * gc.y + bc.y;
    o2.z = (c.z - mean) * rstd * gc.z + bc.z;
    o2.w = (c.w - mean) * rstd * gc.w + bc.w;
    float4* y4 = (float4*)(Y + (size_t)row * 256);
    y4[lane] = o1;
    y4[lane + 32] = o2;
}

// ------------- precompute gemm: C[m,n] = alpha * sum_e A(e,m) * B[e,n] ----
// TA=1: A indexed A[e*lda+m]; TA=0: A[m*lda+e]. B always B[e*ldb+n].
template <bool TA>
__global__ void gemm_pre_kernel(const float* __restrict__ A,
                                const float* __restrict__ Bm,
                                float* __restrict__ C,
                                int M, int Nn, int K, int lda, int ldb,
                                float alpha) {
    __shared__ float As[8][65];
    __shared__ float Bs[8][65];
    int t = threadIdx.x;
    int tx = t & 15, ty = t >> 4;
    int m0 = blockIdx.y * 64, n0 = blockIdx.x * 64;
    float acc[4][4];
    #pragma unroll
    for (int i = 0; i < 4; i++)
        #pragma unroll
        for (int j = 0; j < 4; j++) acc[i][j] = 0.0f;

    for (int k0 = 0; k0 < K; k0 += 8) {
        if (TA) {
            int kk = t >> 6, m = t & 63;
            As[kk][m]     = A[(size_t)(k0 + kk) * lda + m0 + m];
            As[kk + 4][m] = A[(size_t)(k0 + kk + 4) * lda + m0 + m];
        } else {
            int m = t >> 2, k2 = (t & 3) * 2;
            As[k2][m]     = A[(size_t)(m0 + m) * lda + k0 + k2];
            As[k2 + 1][m] = A[(size_t)(m0 + m) * lda + k0 + k2 + 1];
        }
        {
            int kk = t >> 6, n = t & 63;
            Bs[kk][n]     = Bm[(size_t)(k0 + kk) * ldb + n0 + n];
            Bs[kk + 4][n] = Bm[(size_t)(k0 + kk + 4) * ldb + n0 + n];
        }
        __syncthreads();
        #pragma unroll
        for (int kk = 0; kk < 8; kk++) {
            float a[4], b[4];
            #pragma unroll
            for (int i = 0; i < 4; i++) a[i] = As[kk][ty * 4 + i];
            #pragma unroll
            for (int j = 0; j < 4; j++) b[j] = Bs[kk][tx * 4 + j];
            #pragma unroll
            for (int i = 0; i < 4; i++)
                #pragma unroll
                for (int j = 0; j < 4; j++) acc[i][j] += a[i] * b[j];
        }
        __syncthreads();
    }
    #pragma unroll
    for (int i = 0; i < 4; i++)
        #pragma unroll
        for (int j = 0; j < 4; j++)
            C[(size_t)(m0 + ty * 4 + i) * Nn + n0 + tx * 4 + j] = alpha * acc[i][j];
}

// ---- small NT GEMM: C = A[M,K] * W[N,K]^T + bias, 64x64 tile, BK=16 -----
// MODE 0: +bias; 1: +bias, relu; 2: +bias + extraM; 3: +bias + rvec[m]*cvec[n]
template <int MODE>
__global__ void gemm64_kernel(const float* __restrict__ A,
                              const float* __restrict__ W,
                              const float* __restrict__ bias,
                              const float* __restrict__ extraM,
                              const float* __restrict__ rvec,
                              const float* __restrict__ cvec,
                              float* __restrict__ C, int M, int Nn, int K) {
    __shared__ float As[16][68];
    __shared__ float Ws[16][68];
    int t = threadIdx.x, tx = t & 15, ty = t >> 4;
    int m0 = blockIdx.y * 64, n0 = blockIdx.x * 64;
    int lm = t >> 2, lk = (t & 3) * 4;
    float acc[4][4];
    #pragma unroll
    for (int i = 0; i < 4; i++)
        #pragma unroll
        for (int j = 0; j < 4; j++) acc[i][j] = 0.0f;

    for (int k0 = 0; k0 < K; k0 += 16) {
        float4 av = *(const float4*)&A[(size_t)(m0 + lm) * K + k0 + lk];
        As[lk][lm] = av.x; As[lk + 1][lm] = av.y;
        As[lk + 2][lm] = av.z; As[lk + 3][lm] = av.w;
        float4 wv = *(const float4*)&W[(size_t)(n0 + lm) * K + k0 + lk];
        Ws[lk][lm] = wv.x; Ws[lk + 1][lm] = wv.y;
        Ws[lk + 2][lm] = wv.z; Ws[lk + 3][lm] = wv.w;
        __syncthreads();
        #pragma unroll
        for (int kk = 0; kk < 16; kk++) {
            float4 a = *(float4*)&As[kk][ty * 4];
            float4 w = *(float4*)&Ws[kk][tx * 4];
            float ar[4] = {a.x, a.y, a.z, a.w};
            float wr[4] = {w.x, w.y, w.z, w.w};
            #pragma unroll
            for (int i = 0; i < 4; i++)
                #pragma unroll
                for (int j = 0; j < 4; j++) acc[i][j] += ar[i] * wr[j];
        }
        __syncthreads();
    }
    #pragma unroll
    for (int i = 0; i < 4; i++) {
        int r = m0 + ty * 4 + i;
        #pragma unroll
        for (int j = 0; j < 4; j++) {
            int c = n0 + tx * 4 + j;
            float v = acc[i][j] + bias[c];
            if (MODE == 1) v = fmaxf(v, 0.0f);
            if (MODE == 2) v += extraM[(size_t)r * Nn + c];
            if (MODE == 3) v += rvec[r] * cvec[c];
            C[(size_t)r * Nn + c] = v;
        }
    }
}

// --------- fused: logits -> softmax(over s) -> partial attn @ x ----------
#define FUSED_SMEM ((128 * XSTR + S_ * DIN + S_ * 128 + 16) * 4)

__global__ void fused_attn_kernel(const float* __restrict__ X,
                                  const float* __restrict__ QK,
                                  const float* __restrict__ CT,
                                  float* __restrict__ part,
                                  float* __restrict__ rpart,
                                  float* __restrict__ attn_out) {
    extern __shared__ float sm[];
    float* xsm  = sm;                    // [128][XSTR]
    float* qsm  = sm + 128 * XSTR;       // [16][256]
    float* atsm = qsm + S_ * DIN;        // [16][128] red buffer then attn
    float* csm  = atsm + S_ * 128;       // [16]
    int b = blockIdx.y, tile = blockIdx.x, n0 = tile * 128;
    int tid = threadIdx.x;

    const float* xb = X + ((size_t)b * N_ + n0) * DIN;
    for (int e = tid; e < 128 * 64; e += 256) {
        int nl = e >> 6, d4 = (e & 63) * 4;
        float4 v = *(const float4*)&xb[(size_t)nl * DIN + d4];
        *(float4*)&xsm[nl * XSTR + d4] = v;
    }
    for (int e = tid; e < S_ * 64; e += 256) {
        int s = e >> 6, d4 = (e & 63) * 4;
        *(float4*)&qsm[s * DIN + d4] =
            *(const float4*)&QK[((size_t)b * S_ + s) * DIN + d4];
    }
    if (tid < S_) csm[tid] = CT[b * S_ + tid];
    __syncthreads();

    // phase 1: logits. thread = (n, half of d)
    int n = tid & 127, half = tid >> 7;
    int dbase = half * 128;
    float acc[S_];
    #pragma unroll
    for (int s = 0; s < S_; s++) acc[s] = 0.0f;
    const float* xr = xsm + n * XSTR + dbase;
    #pragma unroll 8
    for (int d4 = 0; d4 < 128; d4 += 4) {
        float4 xv = *(const float4*)(xr + d4);
        #pragma unroll
        for (int s = 0; s < S_; s++) {
            float4 qv = *(const float4*)&qsm[s * DIN + dbase + d4];
            acc[s] += xv.x * qv.x + xv.y * qv.y + xv.z * qv.z + xv.w * qv.w;
        }
    }
    if (half) {
        #pragma unroll
        for (int s = 0; s < S_; s++) atsm[s * 128 + n] = acc[s];
    }
    __syncthreads();
    if (!half) {
        float mx = -1e30f;
        #pragma unroll
        for (int s = 0; s < S_; s++) {
            acc[s] = acc[s] + atsm[s * 128 + n] + csm[s];
            mx = fmaxf(mx, acc[s]);
        }
        float sum = 0.0f;
        #pragma unroll
        for (int s = 0; s < S_; s++) { acc[s] = __expf(acc[s] - mx); sum += acc[s]; }
        float inv = 1.0f / sum;
        #pragma unroll
        for (int s = 0; s < S_; s++) {
            float a = acc[s] * inv;
            atsm[s * 128 + n] = a;
            if (attn_out)
                attn_out[((size_t)(b * S_ + s)) * N_ + n0 + n] = a;
        }
    }
    __syncthreads();

    // rowsum of attn per slot (warp 0)
    if (tid < 32) {
        #pragma unroll
        for (int s = 0; s < S_; s++) {
            float v = atsm[s * 128 + tid] + atsm[s * 128 + 32 + tid]
                    + atsm[s * 128 + 64 + tid] + atsm[s * 128 + 96 + tid];
            #pragma unroll
            for (int o = 16; o; o >>= 1) v += __shfl_xor_sync(0xffffffffu, v, o);
            if (tid == 0) rpart[(b * NTILES + tile) * S_ + s] = v;
        }
    }

    // phase 3: uv_partial[s, d] = sum_n attn[s,n] * x[n,d]. thread = d.
    int d = tid;
    float uv[S_];
    #pragma unroll
    for (int s = 0; s < S_; s++) uv[s] = 0.0f;
    #pragma unroll 4
    for (int nn = 0; nn < 128; nn += 4) {
        float x0 = xsm[(nn + 0) * XSTR + d];
        float x1 = xsm[(nn + 1) * XSTR + d];
        float x2 = xsm[(nn + 2) * XSTR + d];
        float x3 = xsm[(nn + 3) * XSTR + d];
        #pragma unroll
        for (int s = 0; s < S_; s++) {
            float4 a = *(const float4*)&atsm[s * 128 + nn];
            uv[s] += a.x * x0 + a.y * x1 + a.z * x2 + a.w * x3;
        }
    }
    float* po = part + ((size_t)(b * NTILES + tile) * S_) * DIN + d;
    #pragma unroll
    for (int s = 0; s < S_; s++) po[(size_t)s * DIN] = uv[s];
}

// ---------------- reductions over tiles -----------------------------------
__global__ void reduce_uv_kernel(const float* __restrict__ part,
                                 float* __restrict__ uv) {
    int idx = blockIdx.x * 256 + threadIdx.x;       // B*S*DIN
    int b = idx >> 12;
    int sd = idx & 4095;
    const float* p = part + (size_t)b * NTILES * 4096 + sd;
    float s = 0.0f;
    #pragma unroll 8
    for (int t = 0; t < NTILES; t++) s += p[(size_t)t * 4096];
    uv[idx] = s;
}

__global__ void reduce_r_kernel(const float* __restrict__ rpart,
                                float* __restrict__ r) {
    int i = threadIdx.x;                            // 512
    int b = i >> 4, s = i & 15;
    const float* p = rpart + b * NTILES * S_ + s;
    float v = 0.0f;
    #pragma unroll 8
    for (int t = 0; t < NTILES; t++) v += p[t * S_];
    r[i] = v;
}

// ---------------- tiny vector precomputes ---------------------------------
__global__ void prep_vecs_kernel(const float* __restrict__ Wq,
                                 const float* __restrict__ Wk,
                                 const float* __restrict__ bk,
                                 const float* __restrict__ bq,
                                 float* __restrict__ us,
                                 float* __restrict__ bqk,
                                 float* __restrict__ c0) {
    int t = threadIdx.x;
    if (blockIdx.x == 0) {
        float s = 0.0f;
        for (int e = 0; e < D_; e++) s += bk[e] * Wq[(size_t)e * D_ + t];
        us[t] = SCALE * s;
        if (t == 0) {
            float c = 0.0f;
            for (int e = 0; e < D_; e++) c += bk[e] * bq[e];
            *c0 = SCALE * c;
        }
    } else {
        float s = 0.0f;
        for (int e = 0; e < D_; e++) s += bq[e] * Wk[(size_t)e * DIN + t];
        bqk[t] = SCALE * s;
    }
}

__global__ void biv_kernel(const float* __restrict__ W_ih,
                           const float* __restrict__ bv,
                           float* __restrict__ biv) {
    int warp = threadIdx.x >> 5, lane = threadIdx.x & 31;
    int r = blockIdx.x * 8 + warp;                  // grid 96 -> 768 rows
    float s = 0.0f;
    #pragma unroll
    for (int e = lane; e < D_; e += 32) s += W_ih[(size_t)r * D_ + e] * bv[e];
    #pragma unroll
    for (int o = 16; o; o >>= 1) s += __shfl_xor_sync(0xffffffffu, s, o);
    if (lane == 0) biv[r] = s;
}

__global__ void cterm_kernel(const float* __restrict__ sn,
                             const float* __restrict__ us,
                             const float* __restrict__ c0,
                             float* __restrict__ ct) {
    int warp = threadIdx.x >> 5, lane = threadIdx.x & 31;
    int row = blockIdx.x * 8 + warp;                // grid 64 -> 512 rows
    const float* x = sn + (size_t)row * D_;
    float s = 0.0f;
    #pragma unroll
    for (int e = lane; e < D_; e += 32) s += x[e] * us[e];
    #pragma unroll
    for (int o = 16; o; o >>= 1) s += __shfl_xor_sync(0xffffffffu, s, o);
    if (lane == 0) ct[row] = s + *c0;
}

// ---------------- GRU pointwise -------------------------------------------
__device__ __forceinline__ float sigmoidf(float x) { return 1.0f / (1.0f + __expf(-x)); }

__global__ void gru_pw_kernel(const float* __restrict__ gi,
                              const float* __restrict__ gh,
                              const float* __restrict__ hprev,
                              float* __restrict__ h) {
    int i = blockIdx.x * 256 + threadIdx.x;
    int row = i >> 8, col = i & 255;
    const float* gir = gi + (size_t)row * 768;
    const float* ghr = gh + (size_t)row * 768;
    float r = sigmoidf(gir[col]       + ghr[col]);
    float z = sigmoidf(gir[col + 256] + ghr[col + 256]);
    float n = tanhf(gir[col + 512] + r * ghr[col + 512]);
    h[i] = (1.0f - z) * n + z * hprev[i];
}

__global__ void copy_kernel(const float* __restrict__ s, float* __restrict__ d, int n) {
    int i = blockIdx.x * 256 + threadIdx.x;
    if (i < n) d[i] = s[i];
}

// ---------------- host side ------------------------------------------------
extern "C" void kernel_launch(void* const* d_in, const int* in_sizes, int n_in,
                              void* d_out, int out_size) {
    const float* inputs     = (const float*)d_in[0];
    const float* init_noise = (const float*)d_in[1];
    const float* slots_mu   = (const float*)d_in[2];
    const float* slots_sig  = (const float*)d_in[3];
    const float* ln_in_g    = (const float*)d_in[4];
    const float* ln_in_b    = (const float*)d_in[5];
    const float* ln_s_g     = (const float*)d_in[6];
    const float* ln_s_b     = (const float*)d_in[7];
    const float* ln_m_g     = (const float*)d_in[8];
    const float* ln_m_b     = (const float*)d_in[9];
    const float* Wk         = (const float*)d_in[10];
    const float* bk         = (const float*)d_in[11];
    const float* Wv         = (const float*)d_in[12];
    const float* bv         = (const float*)d_in[13];
    const float* Wq         = (const float*)d_in[14];
    const float* bq         = (const float*)d_in[15];
    const float* W_ih       = (const float*)d_in[16];
    const float* W_hh       = (const float*)d_in[17];
    const float* b_ih       = (const float*)d_in[18];
    const float* b_hh       = (const float*)d_in[19];
    const float* W1         = (const float*)d_in[20];
    const float* b1         = (const float*)d_in[21];
    const float* W2         = (const float*)d_in[22];
    const float* b2         = (const float*)d_in[23];
    float* out = (float*)d_out;

    float *xln, *slots, *sn, *qk, *ct, *uv, *r, *part, *rpart;
    float *gi, *gh, *h, *m, *t, *Wqk, *Wiv, *us, *bqk, *biv, *c0;
    cudaGetSymbolAddress((void**)&xln,   g_xln);
    cudaGetSymbolAddress((void**)&slots, g_slots);
    cudaGetSymbolAddress((void**)&sn,    g_sn);
    cudaGetSymbolAddress((void**)&qk,    g_qk);
    cudaGetSymbolAddress((void**)&ct,    g_ct);
    cudaGetSymbolAddress((void**)&uv,    g_uv);
    cudaGetSymbolAddress((void**)&r,     g_r);
    cudaGetSymbolAddress((void**)&part,  g_part);
    cudaGetSymbolAddress((void**)&rpart, g_rpart);
    cudaGetSymbolAddress((void**)&gi,    g_gi);
    cudaGetSymbolAddress((void**)&gh,    g_gh);
    cudaGetSymbolAddress((void**)&h,     g_h);
    cudaGetSymbolAddress((void**)&m,     g_m);
    cudaGetSymbolAddress((void**)&t,     g_t);
    cudaGetSymbolAddress((void**)&Wqk,   g_Wqk);
    cudaGetSymbolAddress((void**)&Wiv,   g_Wiv);
    cudaGetSymbolAddress((void**)&us,    g_us);
    cudaGetSymbolAddress((void**)&bqk,   g_bqk);
    cudaGetSymbolAddress((void**)&biv,   g_biv);
    cudaGetSymbolAddress((void**)&c0,    g_c0);

    cudaFuncSetAttribute(fused_attn_kernel,
                         cudaFuncAttributeMaxDynamicSharedMemorySize, FUSED_SMEM);

    const int BND = B_ * N_;        // 131072 rows
    const int BSD = B_ * S_ * D_;   // 131072
    const int BSN = B_ * S_ * N_;   // 2097152
    const int ROWS = B_ * S_;       // 512

    // prologue
    slots_init_kernel<<<BSD / 256, 256>>>(init_noise, slots_mu, slots_sig, slots);
    ln_rows_kernel<<<BND / 8, 256>>>(inputs, ln_in_g, ln_in_b, xln, BND);
    prep_vecs_kernel<<<2, 256>>>(Wq, Wk, bk, bq, us, bqk, c0);
    biv_kernel<<<96, 256>>>(W_ih, bv, biv);
    // Wqk[j,d] = scale * sum_e Wk[e,j] * Wq[e,d]   (TA)
    gemm_pre_kernel<true><<<dim3(D_ / 64, DIN / 64), 256>>>(
        Wk, Wq, Wqk, DIN, D_, D_, DIN, D_, SCALE);
    // Wiv[r,j] = sum_e W_ih[r,e] * Wv[e,j]         (NN)
    gemm_pre_kernel<false><<<dim3(DIN / 64, (3 * D_) / 64), 256>>>(
        W_ih, Wv, Wiv, 3 * D_, DIN, D_, D_, DIN, 1.0f);

    float* attn_out = out + (out_size - BSN);

    for (int it = 0; it < 3; it++) {
        ln_rows_kernel<<<ROWS / 8, 256>>>(slots, ln_s_g, ln_s_b, sn, ROWS);
        // qk = sn @ Wqk^T + bqk (scale folded)
        gemm64_kernel<0><<<dim3(DIN / 64, ROWS / 64), 256>>>(
            sn, Wqk, bqk, nullptr, nullptr, nullptr, qk, ROWS, DIN, D_);
        cterm_kernel<<<ROWS / 8, 256>>>(sn, us, c0, ct);
        fused_attn_kernel<<<dim3(NTILES, B_), 256, FUSED_SMEM>>>(
            xln, qk, ct, part, rpart, (it == 2) ? attn_out : nullptr);
        reduce_uv_kernel<<<(B_ * S_ * DIN) / 256, 256>>>(part, uv);
        reduce_r_kernel<<<1, 512>>>(rpart, r);
        // gi = uv @ Wiv^T + b_ih + r[m]*biv[n]
        gemm64_kernel<3><<<dim3((3 * D_) / 64, ROWS / 64), 256>>>(
            uv, Wiv, b_ih, nullptr, r, biv, gi, ROWS, 3 * D_, DIN);
        // gh = slots @ W_hh^T + b_hh
        gemm64_kernel<0><<<dim3((3 * D_) / 64, ROWS / 64), 256>>>(
            slots, W_hh, b_hh, nullptr, nullptr, nullptr, gh, ROWS, 3 * D_, D_);
        gru_pw_kernel<<<BSD / 256, 256>>>(gi, gh, slots, h);
        ln_rows_kernel<<<ROWS / 8, 256>>>(h, ln_m_g, ln_m_b, m, ROWS);
        // t = relu(m @ W1^T + b1)
        gemm64_kernel<1><<<dim3(H_ / 64, ROWS / 64), 256>>>(
            m, W1, b1, nullptr, nullptr, nullptr, t, ROWS, H_, D_);
        // slots = t @ W2^T + b2 + h
        gemm64_kernel<2><<<dim3(D_ / 64, ROWS / 64), 256>>>(
            t, W2, b2, h, nullptr, nullptr, slots, ROWS, D_, H_);
    }

    copy_kernel<<<BSD / 256, 256>>>(slots, out, BSD);
}

// round 5
// speedup vs baseline: 4.2966x; 1.1633x over previous
#include <cuda_runtime.h>
#include <cstddef>

#define B_  32
#define N_  4096
#define DIN 256
#define D_  256
#define S_  16
#define H_  512
#define EPS 1e-5f
#define SCALE 0.0625f
#define NB 64
#define NT2 (N_/NB)          // 64 tiles
#define XS 260               // xsm row stride (floats)
#define AS 18                // atsm row stride
#define ROWS (B_*S_)         // 512

typedef unsigned long long u64;

__device__ __forceinline__ u64 fma2(u64 a, u64 b, u64 c) {
    u64 d;
    asm("fma.rn.f32x2 %0, %1, %2, %3;" : "=l"(d) : "l"(a), "l"(b), "l"(c));
    return d;
}
__device__ __forceinline__ u64 pack2(float lo, float hi) {
    u64 d;
    asm("mov.b64 %0, {%1, %2};" : "=l"(d) : "f"(lo), "f"(hi));
    return d;
}
__device__ __forceinline__ void unpack2(u64 v, float& lo, float& hi) {
    asm("mov.b64 {%0, %1}, %2;" : "=f"(lo), "=f"(hi) : "l"(v));
}
__device__ __forceinline__ float hsum2(u64 v) {
    float a, b; unpack2(v, a, b); return a + b;
}
__device__ __forceinline__ float sigmoidf(float x) { return 1.0f / (1.0f + __expf(-x)); }

// ---------------- scratch ----------------
__device__ float g_xln [(size_t)B_ * N_ * DIN];
__device__ float g_slots[ROWS * D_];
__device__ float g_qk   [ROWS * DIN];
__device__ float g_ct   [ROWS];
__device__ float g_uv   [ROWS * DIN];
__device__ float g_r    [ROWS];
__device__ float g_part [(size_t)B_ * NT2 * S_ * DIN];   // 33.5 MB
__device__ float g_rpart[B_ * NT2 * S_];
__device__ float g_gi   [ROWS * 3 * D_];
__device__ float g_gh   [ROWS * 3 * D_];
__device__ float g_h    [ROWS * D_];
__device__ float g_m    [ROWS * D_];
__device__ float g_t    [ROWS * H_];
__device__ float g_Wqk  [DIN * D_];
__device__ float g_Wiv  [3 * D_ * DIN];
__device__ float g_us   [D_];
__device__ float g_bqk  [DIN];
__device__ float g_biv  [3 * D_];
__device__ float g_c0   [1];

// ---------------- slots init ----------------
__global__ void slots_init_kernel(const float* __restrict__ noise,
                                  const float* __restrict__ mu,
                                  const float* __restrict__ sigma,
                                  float* __restrict__ slots) {
    int i = blockIdx.x * 256 + threadIdx.x;
    int d = i & (D_ - 1);
    slots[i] = mu[d] + sigma[d] * noise[i];
}

// ---------------- LayerNorm (inputs), warp per 256-row ----------------
__global__ void ln_rows_kernel(const float* __restrict__ X,
                               const float* __restrict__ gg,
                               const float* __restrict__ bb,
                               float* __restrict__ Y, int rows) {
    int warp = threadIdx.x >> 5, lane = threadIdx.x & 31;
    int row = blockIdx.x * 8 + warp;
    if (row >= rows) return;
    const float4* x4 = (const float4*)(X + (size_t)row * 256);
    float4 a = x4[lane];
    float4 c = x4[lane + 32];
    float s  = a.x + a.y + a.z + a.w + c.x + c.y + c.z + c.w;
    float s2 = a.x*a.x + a.y*a.y + a.z*a.z + a.w*a.w
             + c.x*c.x + c.y*c.y + c.z*c.z + c.w*c.w;
    #pragma unroll
    for (int o = 16; o; o >>= 1) {
        s  += __shfl_xor_sync(0xffffffffu, s,  o);
        s2 += __shfl_xor_sync(0xffffffffu, s2, o);
    }
    float mean = s * (1.0f / 256.0f);
    float var  = s2 * (1.0f / 256.0f) - mean * mean;
    float rstd = rsqrtf(var + EPS);
    const float4* g4 = (const float4*)gg;
    const float4* b4 = (const float4*)bb;
    float4 ga = g4[lane], gc = g4[lane + 32];
    float4 ba = b4[lane], bc = b4[lane + 32];
    float4 o1, o2;
    o1.x = (a.x - mean) * rstd * ga.x + ba.x;
    o1.y = (a.y - mean) * rstd * ga.y + ba.y;
    o1.z = (a.z - mean) * rstd * ga.z + ba.z;
    o1.w = (a.w - mean) * rstd * ga.w + ba.w;
    o2.x = (c.x - mean) * rstd * gc.x + bc.x;
    o2.y = (c.y - mean) * rstd * gc.y + bc.y;
    o2.z = (c.z - mean) * rstd * gc.z + bc.z;
    o2.w = (c.w - mean) * rstd * gc.w + bc.w;
    float4* y4 = (float4*)(Y + (size_t)row * 256);
    y4[lane] = o1;
    y4[lane + 32] = o2;
}

// ------------- precompute gemm: C[m,n] = alpha * sum_e A(e,m) * B[e,n] ----
template <bool TA>
__global__ void gemm_pre_kernel(const float* __restrict__ A,
                                const float* __restrict__ Bm,
                                float* __restrict__ C,
                                int M, int Nn, int K, int lda, int ldb,
                                float alpha) {
    __shared__ float As[8][65];
    __shared__ float Bs[8][65];
    int t = threadIdx.x;
    int tx = t & 15, ty = t >> 4;
    int m0 = blockIdx.y * 64, n0 = blockIdx.x * 64;
    float acc[4][4];
    #pragma unroll
    for (int i = 0; i < 4; i++)
        #pragma unroll
        for (int j = 0; j < 4; j++) acc[i][j] = 0.0f;

    for (int k0 = 0; k0 < K; k0 += 8) {
        if (TA) {
            int kk = t >> 6, m = t & 63;
            As[kk][m]     = A[(size_t)(k0 + kk) * lda + m0 + m];
            As[kk + 4][m] = A[(size_t)(k0 + kk + 4) * lda + m0 + m];
        } else {
            int m = t >> 2, k2 = (t & 3) * 2;
            As[k2][m]     = A[(size_t)(m0 + m) * lda + k0 + k2];
            As[k2 + 1][m] = A[(size_t)(m0 + m) * lda + k0 + k2 + 1];
        }
        {
            int kk = t >> 6, n = t & 63;
            Bs[kk][n]     = Bm[(size_t)(k0 + kk) * ldb + n0 + n];
            Bs[kk + 4][n] = Bm[(size_t)(k0 + kk + 4) * ldb + n0 + n];
        }
        __syncthreads();
        #pragma unroll
        for (int kk = 0; kk < 8; kk++) {
            float a[4], b[4];
            #pragma unroll
            for (int i = 0; i < 4; i++) a[i] = As[kk][ty * 4 + i];
            #pragma unroll
            for (int j = 0; j < 4; j++) b[j] = Bs[kk][tx * 4 + j];
            #pragma unroll
            for (int i = 0; i < 4; i++)
                #pragma unroll
                for (int j = 0; j < 4; j++) acc[i][j] += a[i] * b[j];
        }
        __syncthreads();
    }
    #pragma unroll
    for (int i = 0; i < 4; i++)
        #pragma unroll
        for (int j = 0; j < 4; j++)
            C[(size_t)(m0 + ty * 4 + i) * Nn + n0 + tx * 4 + j] = alpha * acc[i][j];
}

// ---- shared gemm body: C = A[.,K]·W[Nn,K]^T + bias, 64x64 tile, f32x2 ----
// mode 0: +bias; 1: relu; 2: +extraM; 3: +rvec[m]*cvec[n]
__device__ __forceinline__ void gemm_body(
    const float* __restrict__ A, const float* __restrict__ W,
    const float* __restrict__ bias, const float* __restrict__ extraM,
    const float* __restrict__ rvec, const float* __restrict__ cvec,
    float* __restrict__ C, int Nn, int K, int mode,
    float* As, float* Ws) {
    int t = threadIdx.x, tx = t & 15, ty = t >> 4;
    int m0 = blockIdx.y * 64, n0 = blockIdx.x * 64;
    int lm = t >> 2, lk = (t & 3) * 4;
    u64 c2[4][2];
    #pragma unroll
    for (int i = 0; i < 4; i++) { c2[i][0] = 0ull; c2[i][1] = 0ull; }

    for (int k0 = 0; k0 < K; k0 += 16) {
        float4 av = *(const float4*)&A[(size_t)(m0 + lm) * K + k0 + lk];
        As[(lk + 0) * 68 + lm] = av.x; As[(lk + 1) * 68 + lm] = av.y;
        As[(lk + 2) * 68 + lm] = av.z; As[(lk + 3) * 68 + lm] = av.w;
        float4 wv = *(const float4*)&W[(size_t)(n0 + lm) * K + k0 + lk];
        Ws[(lk + 0) * 68 + lm] = wv.x; Ws[(lk + 1) * 68 + lm] = wv.y;
        Ws[(lk + 2) * 68 + lm] = wv.z; Ws[(lk + 3) * 68 + lm] = wv.w;
        __syncthreads();
        #pragma unroll
        for (int kk = 0; kk < 16; kk++) {
            float4 a = *(const float4*)&As[kk * 68 + ty * 4];
            ulonglong2 w2 = *(const ulonglong2*)&Ws[kk * 68 + tx * 4];
            float ar[4] = {a.x, a.y, a.z, a.w};
            #pragma unroll
            for (int i = 0; i < 4; i++) {
                u64 a2 = pack2(ar[i], ar[i]);
                c2[i][0] = fma2(a2, w2.x, c2[i][0]);
                c2[i][1] = fma2(a2, w2.y, c2[i][1]);
            }
        }
        __syncthreads();
    }
    #pragma unroll
    for (int i = 0; i < 4; i++) {
        int r = m0 + ty * 4 + i;
        #pragma unroll
        for (int p = 0; p < 2; p++) {
            float v0, v1;
            unpack2(c2[i][p], v0, v1);
            int c0c = n0 + tx * 4 + 2 * p;
            v0 += bias[c0c]; v1 += bias[c0c + 1];
            if (mode == 1) { v0 = fmaxf(v0, 0.0f); v1 = fmaxf(v1, 0.0f); }
            if (mode == 2) {
                v0 += extraM[(size_t)r * Nn + c0c];
                v1 += extraM[(size_t)r * Nn + c0c + 1];
            }
            if (mode == 3) {
                float rv = rvec[r];
                v0 += rv * cvec[c0c]; v1 += rv * cvec[c0c + 1];
            }
            C[(size_t)r * Nn + c0c]     = v0;
            C[(size_t)r * Nn + c0c + 1] = v1;
        }
    }
}

// batched gi/gh gemms (z selects)
__global__ __launch_bounds__(256) void gigh_kernel(
    const float* __restrict__ uv, const float* __restrict__ slots,
    const float* __restrict__ Wiv, const float* __restrict__ Whh,
    const float* __restrict__ bih, const float* __restrict__ bhh,
    const float* __restrict__ r, const float* __restrict__ biv,
    float* __restrict__ gi, float* __restrict__ gh) {
    __shared__ float As[16 * 68];
    __shared__ float Ws[16 * 68];
    if (blockIdx.z == 0)
        gemm_body(uv, Wiv, bih, nullptr, r, biv, gi, 3 * D_, DIN, 3, As, Ws);
    else
        gemm_body(slots, Whh, bhh, nullptr, nullptr, nullptr, gh, 3 * D_, D_, 0, As, Ws);
}

__global__ __launch_bounds__(256) void mlp1_kernel(
    const float* __restrict__ m, const float* __restrict__ W1,
    const float* __restrict__ b1, float* __restrict__ t) {
    __shared__ float As[16 * 68];
    __shared__ float Ws[16 * 68];
    gemm_body(m, W1, b1, nullptr, nullptr, nullptr, t, H_, D_, 1, As, Ws);
}

__global__ __launch_bounds__(256) void mlp2_kernel(
    const float* __restrict__ t, const float* __restrict__ W2,
    const float* __restrict__ b2, const float* __restrict__ h,
    float* __restrict__ outp) {
    __shared__ float As[16 * 68];
    __shared__ float Ws[16 * 68];
    gemm_body(t, W2, b2, h, nullptr, nullptr, outp, D_, H_, 2, As, Ws);
}

// ------- front: LN(slots) -> qk gemm (+bqk) and ct, fused ---------------
// grid (DIN/64=4, ROWS/64=8), 256 threads, dynamic smem: snS[64*XS]+Ws[16*68]
#define FRONT_SMEM ((64 * XS + 16 * 68) * 4)
__global__ __launch_bounds__(256) void front_kernel(
    const float* __restrict__ slots,
    const float* __restrict__ ln_g, const float* __restrict__ ln_b,
    const float* __restrict__ Wqk, const float* __restrict__ bqk,
    const float* __restrict__ us, const float* __restrict__ c0,
    float* __restrict__ qk, float* __restrict__ ct) {
    extern __shared__ float sm[];
    float* snS = sm;                  // [64][XS]
    float* Ws  = sm + 64 * XS;        // [16][68]
    int t = threadIdx.x, w = t >> 5, lane = t & 31;
    int r0 = blockIdx.y * 64, c0b = blockIdx.x * 64;

    // LN: warp w handles 8 local rows
    const float4* g4 = (const float4*)ln_g;
    const float4* b4 = (const float4*)ln_b;
    float4 ga = g4[lane], gc = g4[lane + 32];
    float4 ba = b4[lane], bc = b4[lane + 32];
    for (int rr = 0; rr < 8; rr++) {
        int lr = w * 8 + rr;
        const float4* x4 = (const float4*)(slots + (size_t)(r0 + lr) * 256);
        float4 a = x4[lane], c = x4[lane + 32];
        float s  = a.x + a.y + a.z + a.w + c.x + c.y + c.z + c.w;
        float s2 = a.x*a.x + a.y*a.y + a.z*a.z + a.w*a.w
                 + c.x*c.x + c.y*c.y + c.z*c.z + c.w*c.w;
        #pragma unroll
        for (int o = 16; o; o >>= 1) {
            s  += __shfl_xor_sync(0xffffffffu, s,  o);
            s2 += __shfl_xor_sync(0xffffffffu, s2, o);
        }
        float mean = s * (1.0f / 256.0f);
        float var  = s2 * (1.0f / 256.0f) - mean * mean;
        float rstd = rsqrtf(var + EPS);
        float4 o1, o2;
        o1.x = (a.x - mean) * rstd * ga.x + ba.x;
        o1.y = (a.y - mean) * rstd * ga.y + ba.y;
        o1.z = (a.z - mean) * rstd * ga.z + ba.z;
        o1.w = (a.w - mean) * rstd * ga.w + ba.w;
        o2.x = (c.x - mean) * rstd * gc.x + bc.x;
        o2.y = (c.y - mean) * rstd * gc.y + bc.y;
        o2.z = (c.z - mean) * rstd * gc.z + bc.z;
        o2.w = (c.w - mean) * rstd * gc.w + bc.w;
        *(float4*)&snS[lr * XS + lane * 4] = o1;
        *(float4*)&snS[lr * XS + (lane + 32) * 4] = o2;
    }
    __syncthreads();

    if (blockIdx.x == 0 && t < 64) {
        float s = 0.0f;
        #pragma unroll 8
        for (int e = 0; e < 256; e++) s += snS[t * XS + e] * us[e];
        ct[r0 + t] = s + c0[0];
    }
    __syncthreads();

    // gemm: qk[r, c] = sum_k sn[r,k] * Wqk[c,k]
    int tx = t & 15, ty = t >> 4, lm = t >> 2, lk = (t & 3) * 4;
    u64 c2[4][2];
    #pragma unroll
    for (int i = 0; i < 4; i++) { c2[i][0] = 0ull; c2[i][1] = 0ull; }
    for (int k0 = 0; k0 < 256; k0 += 16) {
        float4 wv = *(const float4*)&Wqk[(size_t)(c0b + lm) * 256 + k0 + lk];
        Ws[(lk + 0) * 68 + lm] = wv.x; Ws[(lk + 1) * 68 + lm] = wv.y;
        Ws[(lk + 2) * 68 + lm] = wv.z; Ws[(lk + 3) * 68 + lm] = wv.w;
        __syncthreads();
        #pragma unroll
        for (int kk = 0; kk < 16; kk++) {
            ulonglong2 w2 = *(const ulonglong2*)&Ws[kk * 68 + tx * 4];
            #pragma unroll
            for (int i = 0; i < 4; i++) {
                float ai = snS[(ty * 4 + i) * XS + k0 + kk];
                u64 a2 = pack2(ai, ai);
                c2[i][0] = fma2(a2, w2.x, c2[i][0]);
                c2[i][1] = fma2(a2, w2.y, c2[i][1]);
            }
        }
        __syncthreads();
    }
    #pragma unroll
    for (int i = 0; i < 4; i++) {
        int r = r0 + ty * 4 + i;
        #pragma unroll
        for (int p = 0; p < 2; p++) {
            float v0, v1;
            unpack2(c2[i][p], v0, v1);
            int cc = c0b + tx * 4 + 2 * p;
            qk[(size_t)r * 256 + cc]     = v0 + bqk[cc];
            qk[(size_t)r * 256 + cc + 1] = v1 + bqk[cc + 1];
        }
    }
}

// --------- fused: logits -> softmax(s) -> partial attn @ x (f32x2) -------
// grid (NT2, B), 256 threads, 2 blocks/SM.
#define FUSED_SMEM ((64 * XS + 16 * 256 + 1024 + 1024 + 64 * AS + 16 + 32) * 4)

__global__ __launch_bounds__(256, 2) void fused_attn_kernel(
    const float* __restrict__ X, const float* __restrict__ QK,
    const float* __restrict__ CT,
    float* __restrict__ part, float* __restrict__ rpart,
    float* __restrict__ attn_out) {
    extern __shared__ float sm[];
    float* xsm  = sm;                       // [64][XS]
    float* qsm  = sm + 64 * XS;             // [16][256]
    float* redA = qsm + 16 * 256;           // [16][64]
    float* redB = redA + 1024;              // [16][64]
    float* atsm = redB + 1024;              // [64][AS]
    float* csm  = atsm + 64 * AS;           // [16]
    float* wred = csm + 16;                 // [2][16]
    int b = blockIdx.y, tile = blockIdx.x, n0 = tile * NB;
    int tid = threadIdx.x;

    const float* xb = X + ((size_t)b * N_ + n0) * DIN;
    #pragma unroll
    for (int e = tid; e < 64 * 64; e += 256) {
        int row = e >> 6, c4 = (e & 63) * 4;
        *(float4*)&xsm[row * XS + c4] = *(const float4*)&xb[(size_t)row * DIN + c4];
    }
    for (int e = tid; e < S_ * 64; e += 256) {
        int s = e >> 6, c4 = (e & 63) * 4;
        *(float4*)&qsm[s * 256 + c4] =
            *(const float4*)&QK[((size_t)b * S_ + s) * DIN + c4];
    }
    if (tid < S_) csm[tid] = CT[b * S_ + tid];
    __syncthreads();

    // ---- phase 1: logits[n][s], thread = (n = tid&63, dq = tid>>6) ----
    int n = tid & 63, dq = tid >> 6;
    int db = dq * 64;
    u64 acc[S_];
    #pragma unroll
    for (int s = 0; s < S_; s++) acc[s] = 0ull;
    const ulonglong2* xr = (const ulonglong2*)(xsm + n * XS + db);
    #pragma unroll 4
    for (int i = 0; i < 16; i++) {
        ulonglong2 xv = xr[i];
        const float* qb = qsm + db + i * 4;
        #pragma unroll
        for (int s = 0; s < S_; s++) {
            ulonglong2 qv = *(const ulonglong2*)(qb + s * 256);
            acc[s] = fma2(xv.x, qv.x, acc[s]);
            acc[s] = fma2(xv.y, qv.y, acc[s]);
        }
    }
    float p[S_];
    #pragma unroll
    for (int s = 0; s < S_; s++) p[s] = hsum2(acc[s]);

    if (dq == 2) {
        #pragma unroll
        for (int s = 0; s < S_; s++) redA[s * 64 + n] = p[s];
    }
    if (dq == 3) {
        #pragma unroll
        for (int s = 0; s < S_; s++) redB[s * 64 + n] = p[s];
    }
    __syncthreads();
    if (dq == 0) {
        #pragma unroll
        for (int s = 0; s < S_; s++) p[s] += redA[s * 64 + n];
    }
    if (dq == 1) {
        #pragma unroll
        for (int s = 0; s < S_; s++) {
            p[s] += redB[s * 64 + n];
            redB[s * 64 + n] = p[s];
        }
    }
    __syncthreads();

    // ---- softmax over s (threads 0..63, one per n) + rowsum ----
    if (tid < 64) {
        float mx = -1e30f;
        #pragma unroll
        for (int s = 0; s < S_; s++) {
            p[s] = p[s] + redB[s * 64 + n] + csm[s];
            mx = fmaxf(mx, p[s]);
        }
        float sum = 0.0f;
        #pragma unroll
        for (int s = 0; s < S_; s++) { p[s] = __expf(p[s] - mx); sum += p[s]; }
        float inv = 1.0f / sum;
        #pragma unroll
        for (int s = 0; s < S_; s++) {
            float a = p[s] * inv;
            p[s] = a;
            atsm[n * AS + s] = a;
            if (attn_out)
                attn_out[((size_t)(b * S_ + s)) * N_ + n0 + n] = a;
        }
        #pragma unroll
        for (int s = 0; s < S_; s++) {
            float v = p[s];
            #pragma unroll
            for (int o = 16; o; o >>= 1) v += __shfl_xor_sync(0xffffffffu, v, o);
            if ((tid & 31) == 0) wred[(tid >> 5) * 16 + s] = v;
        }
    }
    __syncthreads();
    if (tid < S_)
        rpart[((size_t)b * NT2 + tile) * S_ + tid] = wred[tid] + wred[16 + tid];

    // ---- phase 3: uv_partial[s][d] = sum_n attn[n][s]*x[n][d], thread=d ----
    u64 uacc[8];
    #pragma unroll
    for (int sp = 0; sp < 8; sp++) uacc[sp] = 0ull;
    #pragma unroll 4
    for (int nn = 0; nn < NB; nn++) {
        float xv = xsm[nn * XS + tid];
        u64 x2 = pack2(xv, xv);
        const u64* arow = (const u64*)(atsm + nn * AS);
        #pragma unroll
        for (int sp = 0; sp < 8; sp++)
            uacc[sp] = fma2(x2, arow[sp], uacc[sp]);
    }
    float* po = part + ((size_t)(b * NT2 + tile) * S_) * DIN + tid;
    #pragma unroll
    for (int sp = 0; sp < 8; sp++) {
        float v0, v1;
        unpack2(uacc[sp], v0, v1);
        po[(size_t)(2 * sp) * DIN]     = v0;
        po[(size_t)(2 * sp + 1) * DIN] = v1;
    }
}

// ---------------- merged reductions ---------------------------------------
__global__ void reduce_kernel(const float* __restrict__ part,
                              const float* __restrict__ rpart,
                              float* __restrict__ uv,
                              float* __restrict__ r) {
    int idx = blockIdx.x * 256 + threadIdx.x;       // B*S*DIN
    int b = idx >> 12, sd = idx & 4095;
    const float* p = part + (size_t)b * NT2 * 4096 + sd;
    float s = 0.0f;
    #pragma unroll 8
    for (int t = 0; t < NT2; t++) s += p[(size_t)t * 4096];
    uv[idx] = s;
    if (blockIdx.x == 0) {
        for (int i = threadIdx.x; i < ROWS; i += 256) {
            const float* rp = rpart + (i >> 4) * NT2 * S_ + (i & 15);
            float v = 0.0f;
            #pragma unroll 8
            for (int t = 0; t < NT2; t++) v += rp[t * S_];
            r[i] = v;
        }
    }
}

// ---------------- GRU + LN(m) fused (warp per row) ------------------------
__global__ void gru_ln_kernel(const float* __restrict__ gi,
                              const float* __restrict__ gh,
                              const float* __restrict__ slots,
                              const float* __restrict__ gg,
                              const float* __restrict__ bb,
                              float* __restrict__ h,
                              float* __restrict__ m) {
    int w = threadIdx.x >> 5, lane = threadIdx.x & 31;
    int row = blockIdx.x * 8 + w;
    const float* gir = gi + (size_t)row * 768;
    const float* ghr = gh + (size_t)row * 768;
    const float* hp  = slots + (size_t)row * 256;
    int c1 = lane * 4, c2i = c1 + 128;
    float hv[8];
    #pragma unroll
    for (int g = 0; g < 2; g++) {
        int c = g ? c2i : c1;
        float4 ir = *(const float4*)&gir[c];
        float4 hr = *(const float4*)&ghr[c];
        float4 iz = *(const float4*)&gir[c + 256];
        float4 hz = *(const float4*)&ghr[c + 256];
        float4 in = *(const float4*)&gir[c + 512];
        float4 hn = *(const float4*)&ghr[c + 512];
        float4 pv = *(const float4*)&hp[c];
        float rr, zz, nn;
        rr = sigmoidf(ir.x + hr.x); zz = sigmoidf(iz.x + hz.x);
        nn = tanhf(in.x + rr * hn.x); hv[g*4+0] = (1.0f - zz) * nn + zz * pv.x;
        rr = sigmoidf(ir.y + hr.y); zz = sigmoidf(iz.y + hz.y);
        nn = tanhf(in.y + rr * hn.y); hv[g*4+1] = (1.0f - zz) * nn + zz * pv.y;
        rr = sigmoidf(ir.z + hr.z); zz = sigmoidf(iz.z + hz.z);
        nn = tanhf(in.z + rr * hn.z); hv[g*4+2] = (1.0f - zz) * nn + zz * pv.z;
        rr = sigmoidf(ir.w + hr.w); zz = sigmoidf(iz.w + hz.w);
        nn = tanhf(in.w + rr * hn.w); hv[g*4+3] = (1.0f - zz) * nn + zz * pv.w;
    }
    float s = 0.0f, s2 = 0.0f;
    #pragma unroll
    for (int i = 0; i < 8; i++) { s += hv[i]; s2 += hv[i] * hv[i]; }
    #pragma unroll
    for (int o = 16; o; o >>= 1) {
        s  += __shfl_xor_sync(0xffffffffu, s,  o);
        s2 += __shfl_xor_sync(0xffffffffu, s2, o);
    }
    float mean = s * (1.0f / 256.0f);
    float var  = s2 * (1.0f / 256.0f) - mean * mean;
    float rstd = rsqrtf(var + EPS);
    float* hrow = h + (size_t)row * 256;
    float* mrow = m + (size_t)row * 256;
    #pragma unroll
    for (int g = 0; g < 2; g++) {
        int c = g ? c2i : c1;
        float4 gv = *(const float4*)&gg[c];
        float4 bv = *(const float4*)&bb[c];
        float4 hvv = make_float4(hv[g*4+0], hv[g*4+1], hv[g*4+2], hv[g*4+3]);
        float4 mv;
        mv.x = (hvv.x - mean) * rstd * gv.x + bv.x;
        mv.y = (hvv.y - mean) * rstd * gv.y + bv.y;
        mv.z = (hvv.z - mean) * rstd * gv.z + bv.z;
        mv.w = (hvv.w - mean) * rstd * gv.w + bv.w;
        *(float4*)&hrow[c] = hvv;
        *(float4*)&mrow[c] = mv;
    }
}

// ---------------- prologue vector precomputes (merged) --------------------
__global__ void prep_kernel(const float* __restrict__ Wq,
                            const float* __restrict__ Wk,
                            const float* __restrict__ bk,
                            const float* __restrict__ bq,
                            const float* __restrict__ W_ih,
                            const float* __restrict__ bv,
                            float* __restrict__ us,
                            float* __restrict__ bqk,
                            float* __restrict__ c0,
                            float* __restrict__ biv) {
    int bx = blockIdx.x, t = threadIdx.x;
    if (bx < 96) {
        int warp = t >> 5, lane = t & 31;
        int r = bx * 8 + warp;
        float s = 0.0f;
        #pragma unroll
        for (int e = lane; e < D_; e += 32) s += W_ih[(size_t)r * D_ + e] * bv[e];
        #pragma unroll
        for (int o = 16; o; o >>= 1) s += __shfl_xor_sync(0xffffffffu, s, o);
        if (lane == 0) biv[r] = s;
    } else if (bx == 96) {
        float s = 0.0f;
        for (int e = 0; e < D_; e++) s += bk[e] * Wq[(size_t)e * D_ + t];
        us[t] = SCALE * s;
        if (t == 0) {
            float c = 0.0f;
            for (int e = 0; e < D_; e++) c += bk[e] * bq[e];
            *c0 = SCALE * c;
        }
    } else {
        float s = 0.0f;
        for (int e = 0; e < D_; e++) s += bq[e] * Wk[(size_t)e * DIN + t];
        bqk[t] = SCALE * s;
    }
}

// ---------------- host side ------------------------------------------------
extern "C" void kernel_launch(void* const* d_in, const int* in_sizes, int n_in,
                              void* d_out, int out_size) {
    const float* inputs     = (const float*)d_in[0];
    const float* init_noise = (const float*)d_in[1];
    const float* slots_mu   = (const float*)d_in[2];
    const float* slots_sig  = (const float*)d_in[3];
    const float* ln_in_g    = (const float*)d_in[4];
    const float* ln_in_b    = (const float*)d_in[5];
    const float* ln_s_g     = (const float*)d_in[6];
    const float* ln_s_b     = (const float*)d_in[7];
    const float* ln_m_g     = (const float*)d_in[8];
    const float* ln_m_b     = (const float*)d_in[9];
    const float* Wk         = (const float*)d_in[10];
    const float* bk         = (const float*)d_in[11];
    const float* Wv         = (const float*)d_in[12];
    const float* bv         = (const float*)d_in[13];
    const float* Wq         = (const float*)d_in[14];
    const float* bq         = (const float*)d_in[15];
    const float* W_ih       = (const float*)d_in[16];
    const float* W_hh       = (const float*)d_in[17];
    const float* b_ih       = (const float*)d_in[18];
    const float* b_hh       = (const float*)d_in[19];
    const float* W1         = (const float*)d_in[20];
    const float* b1         = (const float*)d_in[21];
    const float* W2         = (const float*)d_in[22];
    const float* b2         = (const float*)d_in[23];
    float* out = (float*)d_out;

    float *xln, *slots, *qk, *ct, *uv, *r, *part, *rpart;
    float *gi, *gh, *h, *m, *t, *Wqk, *Wiv, *us, *bqk, *biv, *c0;
    cudaGetSymbolAddress((void**)&xln,   g_xln);
    cudaGetSymbolAddress((void**)&slots, g_slots);
    cudaGetSymbolAddress((void**)&qk,    g_qk);
    cudaGetSymbolAddress((void**)&ct,    g_ct);
    cudaGetSymbolAddress((void**)&uv,    g_uv);
    cudaGetSymbolAddress((void**)&r,     g_r);
    cudaGetSymbolAddress((void**)&part,  g_part);
    cudaGetSymbolAddress((void**)&rpart, g_rpart);
    cudaGetSymbolAddress((void**)&gi,    g_gi);
    cudaGetSymbolAddress((void**)&gh,    g_gh);
    cudaGetSymbolAddress((void**)&h,     g_h);
    cudaGetSymbolAddress((void**)&m,     g_m);
    cudaGetSymbolAddress((void**)&t,     g_t);
    cudaGetSymbolAddress((void**)&Wqk,   g_Wqk);
    cudaGetSymbolAddress((void**)&Wiv,   g_Wiv);
    cudaGetSymbolAddress((void**)&us,    g_us);
    cudaGetSymbolAddress((void**)&bqk,   g_bqk);
    cudaGetSymbolAddress((void**)&biv,   g_biv);
    cudaGetSymbolAddress((void**)&c0,    g_c0);

    cudaFuncSetAttribute(fused_attn_kernel,
                         cudaFuncAttributeMaxDynamicSharedMemorySize, FUSED_SMEM);
    cudaFuncSetAttribute(front_kernel,
                         cudaFuncAttributeMaxDynamicSharedMemorySize, FRONT_SMEM);

    const int BND = B_ * N_;
    const int BSD = ROWS * D_;      // 131072
    const int BSN = B_ * S_ * N_;   // 2097152

    // prologue
    slots_init_kernel<<<BSD / 256, 256>>>(init_noise, slots_mu, slots_sig, slots);
    ln_rows_kernel<<<BND / 8, 256>>>(inputs, ln_in_g, ln_in_b, xln, BND);
    prep_kernel<<<98, 256>>>(Wq, Wk, bk, bq, W_ih, bv, us, bqk, c0, biv);
    gemm_pre_kernel<true><<<dim3(D_ / 64, DIN / 64), 256>>>(
        Wk, Wq, Wqk, DIN, D_, D_, DIN, D_, SCALE);
    gemm_pre_kernel<false><<<dim3(DIN / 64, (3 * D_) / 64), 256>>>(
        W_ih, Wv, Wiv, 3 * D_, DIN, D_, D_, DIN, 1.0f);

    float* attn_out = out + (out_size - BSN);

    for (int it = 0; it < 3; it++) {
        front_kernel<<<dim3(DIN / 64, ROWS / 64), 256, FRONT_SMEM>>>(
            slots, ln_s_g, ln_s_b, Wqk, bqk, us, c0, qk, ct);
        fused_attn_kernel<<<dim3(NT2, B_), 256, FUSED_SMEM>>>(
            xln, qk, ct, part, rpart, (it == 2) ? attn_out : nullptr);
        reduce_kernel<<<(ROWS * DIN) / 256, 256>>>(part, rpart, uv, r);
        gigh_kernel<<<dim3((3 * D_) / 64, ROWS / 64, 2), 256>>>(
            uv, slots, Wiv, W_hh, b_ih, b_hh, r, biv, gi, gh);
        gru_ln_kernel<<<ROWS / 8, 256>>>(gi, gh, slots, ln_m_g, ln_m_b, h, m);
        mlp1_kernel<<<dim3(H_ / 64, ROWS / 64), 256>>>(m, W1, b1, t);
        mlp2_kernel<<<dim3(D_ / 64, ROWS / 64), 256>>>(
            t, W2, b2, h, (it == 2) ? out : slots);
    }
}